// round 10
// baseline (speedup 1.0000x reference)
#include <cuda_runtime.h>

#define N_NODES 100000
#define N_EDGES 1600000
#define HID 64
#define NGRAPH 4096
#define BN_EPS 1e-5f
#define SCAN_B 1024
#define SCAN_NB ((N_NODES + SCAN_B - 1) / SCAN_B)   // 98
#define N_TILES (N_NODES / 16)                      // 6250 (exact)
#define GATH_GRID 592

// ---------------- scratch (device globals; no allocations) ----------------
// g_h has one extra row (index N_NODES) kept all-zero: padded gather lanes
// point at it and contribute nothing.
__device__ __align__(16) float g_h[(N_NODES + 1) * HID]; // pre-scaled h' = h*dinv
__device__ __align__(16) float g_y[N_NODES * HID];       // post-relu layer output
__device__ int   g_cnt[N_NODES];                         // in-degree (histogram)
__device__ float g_dinv[N_NODES];
__device__ int   g_rowptr[N_NODES];
__device__ int   g_cursor[N_NODES];
__device__ int   g_eidx[N_EDGES];                        // src idx sorted by dst
__device__ int   g_blksum[SCAN_NB];
__device__ float g_stats[2][2 * HID];                    // ping-pong [sum, sumsq]

// ---------------- f32x2 helpers ----------------
__device__ __forceinline__ void ffma2(unsigned long long& d,
                                      unsigned long long a,
                                      unsigned long long b) {
    asm("fma.rn.f32x2 %0, %1, %2, %0;" : "+l"(d) : "l"(a), "l"(b));
}
__device__ __forceinline__ unsigned long long fpack2(float x) {
    unsigned long long r;
    unsigned u = __float_as_uint(x);
    asm("mov.b64 %0, {%1, %1};" : "=l"(r) : "r"(u));
    return r;
}
__device__ __forceinline__ float2 funpack2(unsigned long long v) {
    unsigned lo, hi;
    asm("mov.b64 {%0, %1}, %2;" : "=r"(lo), "=r"(hi) : "l"(v));
    float2 f;
    f.x = __uint_as_float(lo);
    f.y = __uint_as_float(hi);
    return f;
}

// ---------------- CSR build ----------------
__global__ void hist_kernel(const int* __restrict__ dst) {
    int e = blockIdx.x * blockDim.x + threadIdx.x;
    if (e < N_EDGES) {
        asm volatile("red.global.add.u32 [%0], %1;"
                     :: "l"(&g_cnt[dst[e]]), "r"(1) : "memory");
    }
}

__global__ __launch_bounds__(SCAN_B) void scan1_kernel() {
    __shared__ int sm[SCAN_B];
    int t = threadIdx.x;
    int i = blockIdx.x * SCAN_B + t;
    int v = (i < N_NODES) ? g_cnt[i] : 0;
    sm[t] = v;
    __syncthreads();
    for (int off = 1; off < SCAN_B; off <<= 1) {
        int x = (t >= off) ? sm[t - off] : 0;
        __syncthreads();
        sm[t] += x;
        __syncthreads();
    }
    if (i < N_NODES) g_rowptr[i] = sm[t] - v;  // exclusive (block-local)
    if (t == SCAN_B - 1) g_blksum[blockIdx.x] = sm[t];
}

// scan finalize: each block re-scans the 98 block sums itself, applies offset,
// inits cursor + dinv.
__global__ __launch_bounds__(SCAN_B) void scan23_kernel() {
    __shared__ int sb[128];
    __shared__ int sv[128];
    int t = threadIdx.x;
    if (t < 128) {
        int v = (t < SCAN_NB) ? g_blksum[t] : 0;
        sb[t] = v;
        sv[t] = v;
    }
    __syncthreads();
    for (int off = 1; off < 128; off <<= 1) {
        int x = (t >= off && t < 128) ? sb[t - off] : 0;
        __syncthreads();
        if (t < 128) sb[t] += x;
        __syncthreads();
    }
    int offset = sb[blockIdx.x] - sv[blockIdx.x];
    int i = blockIdx.x * SCAN_B + t;
    if (i < N_NODES) {
        int r = g_rowptr[i] + offset;
        g_rowptr[i] = r;
        g_cursor[i] = r;
        g_dinv[i] = rsqrtf((float)g_cnt[i] + 1.f);
    }
}

// fill: no dinv work, 4-byte scattered store only
__global__ void fill_kernel(const int* __restrict__ src, const int* __restrict__ dst) {
    int e = blockIdx.x * blockDim.x + threadIdx.x;
    if (e < N_EDGES) {
        int s = src[e];
        int d = dst[e];
        int pos = atomicAdd(&g_cursor[d], 1);
        g_eidx[pos] = s;
    }
}

// ---------------- GEMM: h' = (X @ W) * dinv[row] ---------------------------
// Tile: 32 nodes x 64 cols per 256-thread block. Thread = 2 nodes x 4 cols.
// X staged into smem PRE-DUPLICATED as 64-bit (v,v) so the inner loop needs
// no packing: per k = 2 LDS.64 (x-dup) + 1 LDS.128 (w col-pairs) + 4 FFMA2.
template <int IN, bool FROM_Y>
__global__ __launch_bounds__(256) void gemm_kernel(const float* __restrict__ X,
                                                   const float* __restrict__ W,
                                                   const float* __restrict__ gam,
                                                   const float* __restrict__ bet,
                                                   int rdp, int wrp) {
    constexpr int IN_P = (IN + 3) & ~3;  // 76 for 75, 64 for 64
    __shared__ __align__(16) float Ws[IN_P * HID];                 // 19456 B
    __shared__ __align__(16) unsigned long long Xd[32 * IN_P];     // 19456 B
    __shared__ float s_a[HID];
    __shared__ float s_dd[HID];
    __shared__ float s_dv[32];

    int tid = threadIdx.x;

    if (tid < 2 * HID) g_stats[wrp][tid] = 0.f;

    // stage W (zero-pad rows IN..IN_P)
    for (int i = tid; i < IN_P * HID; i += 256)
        Ws[i] = (i < IN * HID) ? W[i] : 0.f;

    if (FROM_Y && tid < HID) {
        float mean = g_stats[rdp][tid] * (1.f / N_NODES);
        float var  = g_stats[rdp][HID + tid] * (1.f / N_NODES) - mean * mean;
        float a = gam[tid] * rsqrtf(var + BN_EPS);
        s_a[tid]  = a;
        s_dd[tid] = bet[tid] - mean * a;
    }

    int base = blockIdx.x * 32;
    if (tid < 32) {
        int gn = base + tid;
        s_dv[tid] = (gn < N_NODES) ? g_dinv[gn] : 0.f;
    }
    __syncthreads();  // s_a/s_dd ready before staging reads them

    // stage X duplicated: group of 16 threads per node row, 16 consecutive k
    {
        int n_s = tid >> 4;   // 0..15
        int k_s = tid & 15;
        for (int nn = n_s; nn < 32; nn += 16) {
            int gn = base + nn;
            for (int k = k_s; k < IN; k += 16) {
                float v = 0.f;
                if (gn < N_NODES) {
                    if (FROM_Y) v = g_y[gn * HID + k] * s_a[k] + s_dd[k];
                    else        v = X[gn * IN + k];
                }
                Xd[nn * IN_P + k] = fpack2(v);
            }
            if (IN_P != IN && k_s == 0) {
#pragma unroll
                for (int k = IN; k < IN_P; k++) Xd[nn * IN_P + k] = 0ull;
            }
        }
    }
    __syncthreads();

    int tx = tid & 15, ty = tid >> 4;
    int c0 = tx * 4;
    int n0 = ty * 2;

    unsigned long long acc00 = 0ull, acc01 = 0ull, acc10 = 0ull, acc11 = 0ull;

#pragma unroll 4
    for (int k = 0; k < IN_P; k++) {
        ulonglong2 wq = *(const ulonglong2*)&Ws[k * HID + c0];
        unsigned long long x0 = Xd[(n0 + 0) * IN_P + k];
        unsigned long long x1 = Xd[(n0 + 1) * IN_P + k];
        ffma2(acc00, x0, wq.x); ffma2(acc01, x0, wq.y);
        ffma2(acc10, x1, wq.x); ffma2(acc11, x1, wq.y);
    }

#pragma unroll
    for (int i = 0; i < 2; i++) {
        int gn = base + n0 + i;
        if (gn >= N_NODES) break;
        float dv = s_dv[n0 + i];
        float2 lo = funpack2(i == 0 ? acc00 : acc10);
        float2 hi = funpack2(i == 0 ? acc01 : acc11);
        float4 h;
        h.x = lo.x * dv; h.y = lo.y * dv; h.z = hi.x * dv; h.w = hi.y * dv;
        *(float4*)&g_h[gn * HID + c0] = h;
    }
}

// ---------------- gather aggregation + relu + BN stats ----------------
// y[n] = relu( dinv[n]*(h'[n] + Sum h'[src]) + b ). No per-edge weight.
// Padded lanes index the zero row at N_NODES (L1-hot). Metadata prefetched
// one chunk ahead; group-uniform early-outs every 4 edges cut padded work.
__global__ __launch_bounds__(256) void gather_kernel(const float* __restrict__ bias,
                                                     int wrp) {
    __shared__ float s_b[HID];
    __shared__ float sm_s[16][HID + 4];
    __shared__ float sm_q[16][HID + 4];

    int tid   = threadIdx.x;
    int grp   = tid >> 4;
    int lane  = tid & 15;
    unsigned hmask = 0xFFFFu << ((tid & 31) & 16);  // this half-warp's lanes
    int c4    = lane * 4;

    if (tid < HID) s_b[tid] = bias[tid];
    __syncthreads();
    float4 bb = *(const float4*)&s_b[c4];

    float4 s4 = {0.f, 0.f, 0.f, 0.f};
    float4 q4 = {0.f, 0.f, 0.f, 0.f};

    for (int tile = blockIdx.x; tile < N_TILES; tile += GATH_GRID) {
        int n = tile * 16 + grp;
        float dv = g_dinv[n];

        float4 acc = *(const float4*)&g_h[n * HID + c4];  // self term h'[n]

        int start = g_rowptr[n];
        int len   = g_cnt[n];

        // prefetch first metadata chunk (pad -> zero row)
        int pre = (lane < len) ? g_eidx[start + lane] : N_NODES;

        for (int j0 = 0; j0 < len; j0 += 16) {
            int sidx = pre;
            int nj = j0 + 16 + lane;
            pre = (nj < len) ? g_eidx[start + nj] : N_NODES;

#pragma unroll
            for (int j = 0; j < 4; j++) {
                int s = __shfl_sync(hmask, sidx, j, 16);
                float4 hv = *(const float4*)&g_h[s * HID + c4];
                acc.x += hv.x; acc.y += hv.y;
                acc.z += hv.z; acc.w += hv.w;
            }
            if (len > j0 + 4) {
#pragma unroll
                for (int j = 4; j < 8; j++) {
                    int s = __shfl_sync(hmask, sidx, j, 16);
                    float4 hv = *(const float4*)&g_h[s * HID + c4];
                    acc.x += hv.x; acc.y += hv.y;
                    acc.z += hv.z; acc.w += hv.w;
                }
            }
            if (len > j0 + 8) {
#pragma unroll
                for (int j = 8; j < 12; j++) {
                    int s = __shfl_sync(hmask, sidx, j, 16);
                    float4 hv = *(const float4*)&g_h[s * HID + c4];
                    acc.x += hv.x; acc.y += hv.y;
                    acc.z += hv.z; acc.w += hv.w;
                }
            }
            if (len > j0 + 12) {
#pragma unroll
                for (int j = 12; j < 16; j++) {
                    int s = __shfl_sync(hmask, sidx, j, 16);
                    float4 hv = *(const float4*)&g_h[s * HID + c4];
                    acc.x += hv.x; acc.y += hv.y;
                    acc.z += hv.z; acc.w += hv.w;
                }
            }
        }

        acc.x = fmaxf(acc.x * dv + bb.x, 0.f);
        acc.y = fmaxf(acc.y * dv + bb.y, 0.f);
        acc.z = fmaxf(acc.z * dv + bb.z, 0.f);
        acc.w = fmaxf(acc.w * dv + bb.w, 0.f);
        *(float4*)&g_y[n * HID + c4] = acc;

        s4.x += acc.x; q4.x += acc.x * acc.x;
        s4.y += acc.y; q4.y += acc.y * acc.y;
        s4.z += acc.z; q4.z += acc.z * acc.z;
        s4.w += acc.w; q4.w += acc.w * acc.w;
    }

    sm_s[grp][c4 + 0] = s4.x; sm_q[grp][c4 + 0] = q4.x;
    sm_s[grp][c4 + 1] = s4.y; sm_q[grp][c4 + 1] = q4.y;
    sm_s[grp][c4 + 2] = s4.z; sm_q[grp][c4 + 2] = q4.z;
    sm_s[grp][c4 + 3] = s4.w; sm_q[grp][c4 + 3] = q4.w;
    __syncthreads();
    if (tid < HID) {
        float s = 0.f, q = 0.f;
#pragma unroll
        for (int r = 0; r < 16; r++) {
            s += sm_s[r][tid];
            q += sm_q[r][tid];
        }
        asm volatile("red.global.add.f32 [%0], %1;" :: "l"(&g_stats[wrp][tid]), "f"(s) : "memory");
        asm volatile("red.global.add.f32 [%0], %1;" :: "l"(&g_stats[wrp][HID + tid]), "f"(q) : "memory");
    }
}

// ---------------- global add pool (applies final BN affine) ----------------
__global__ __launch_bounds__(256) void pool_kernel(const int* __restrict__ batch,
                                                   float* __restrict__ out,
                                                   const float* __restrict__ gam,
                                                   const float* __restrict__ bet) {
    __shared__ float s_a[HID];
    __shared__ float s_d[HID];
    int tid = threadIdx.x;
    if (tid < HID) {
        float mean = g_stats[1][tid] * (1.f / N_NODES);
        float var  = g_stats[1][HID + tid] * (1.f / N_NODES) - mean * mean;
        float a = gam[tid] * rsqrtf(var + BN_EPS);
        s_a[tid] = a;
        s_d[tid] = bet[tid] - mean * a;
    }
    __syncthreads();

    int grp = tid >> 4, lane = tid & 15;
    int c4 = lane * 4;
    float4 a4 = *(const float4*)&s_a[c4];
    float4 d4 = *(const float4*)&s_d[c4];

    int base = blockIdx.x * 256 + grp * 16;
    float4 run = {0.f, 0.f, 0.f, 0.f};
    int cur = -1;
    for (int i = 0; i < 16; i++) {
        int n = base + i;
        if (n >= N_NODES) break;
        int bt = batch[n];
        if (bt != cur) {
            if (cur >= 0) {
                asm volatile("red.global.add.v4.f32 [%0], {%1,%2,%3,%4};"
                             :: "l"(&out[cur * HID + c4]),
                                "f"(run.x), "f"(run.y), "f"(run.z), "f"(run.w) : "memory");
            }
            run.x = run.y = run.z = run.w = 0.f;
            cur = bt;
        }
        float4 v = *(const float4*)&g_y[n * HID + c4];
        run.x += v.x * a4.x + d4.x;
        run.y += v.y * a4.y + d4.y;
        run.z += v.z * a4.z + d4.z;
        run.w += v.w * a4.w + d4.w;
    }
    if (cur >= 0) {
        asm volatile("red.global.add.v4.f32 [%0], {%1,%2,%3,%4};"
                     :: "l"(&out[cur * HID + c4]),
                        "f"(run.x), "f"(run.y), "f"(run.z), "f"(run.w) : "memory");
    }
}

// ---------------- launch ----------------
extern "C" void kernel_launch(void* const* d_in, const int* in_sizes, int n_in,
                              void* d_out, int out_size) {
    const float* x     = (const float*)d_in[0];
    const int*   src   = (const int*)d_in[1];
    const int*   dst   = (const int*)d_in[2];
    const int*   batch = (const int*)d_in[3];
    const float* W[4];
    const float* b[4];
    const float* g[4];
    const float* be[4];
    for (int i = 0; i < 4; i++) {
        W[i]  = (const float*)d_in[4 + 4 * i];
        b[i]  = (const float*)d_in[5 + 4 * i];
        g[i]  = (const float*)d_in[6 + 4 * i];
        be[i] = (const float*)d_in[7 + 4 * i];
    }
    float* out = (float*)d_out;

    const int NB_EDGES = (N_EDGES + 255) / 256;   // 6250
    const int NB_GEMM  = (N_NODES + 31) / 32;     // 3125
    const int NB_NODES = (N_NODES + 255) / 256;   // 391

    void* p_cnt = nullptr;
    cudaGetSymbolAddress(&p_cnt, g_cnt);
    cudaMemsetAsync(p_cnt, 0, N_NODES * sizeof(int), 0);

    hist_kernel<<<NB_EDGES, 256>>>(dst);
    scan1_kernel<<<SCAN_NB, SCAN_B>>>();
    scan23_kernel<<<SCAN_NB, SCAN_B>>>();   // produces dinv

    // gemm1 before fill so the ncu capture slot lands on it again
    gemm_kernel<75, false><<<NB_GEMM, 256>>>(x, W[0], nullptr, nullptr, 0, 0);
    fill_kernel<<<NB_EDGES, 256>>>(src, dst);

    // zero row N_NODES of g_h (target of padded gather lanes)
    void* p_h = nullptr;
    cudaGetSymbolAddress(&p_h, g_h);
    cudaMemsetAsync((char*)p_h + (size_t)N_NODES * HID * sizeof(float), 0,
                    HID * sizeof(float), 0);

    gather_kernel<<<GATH_GRID, 256>>>(b[0], 0);

    // layers 2..4
    for (int l = 1; l < 4; l++) {
        gemm_kernel<64, true><<<NB_GEMM, 256>>>(nullptr, W[l], g[l - 1], be[l - 1],
                                                (l - 1) & 1, l & 1);
        gather_kernel<<<GATH_GRID, 256>>>(b[l], l & 1);
    }

    cudaMemsetAsync(d_out, 0, (size_t)out_size * sizeof(float), 0);
    pool_kernel<<<NB_NODES, 256>>>(batch, out, g[3], be[3]);
}

// round 11
// speedup vs baseline: 1.1687x; 1.1687x over previous
#include <cuda_runtime.h>

#define N_NODES 100000
#define N_EDGES 1600000
#define HID 64
#define NGRAPH 4096
#define BN_EPS 1e-5f
#define SCAN_B 1024
#define SCAN_NB ((N_NODES + SCAN_B - 1) / SCAN_B)   // 98
#define N_TILES (N_NODES / 16)                      // 6250 (exact)
#define GATH_GRID 592
#define GEMM_GRID 444
#define GEMM_NT ((N_NODES + 63) / 64)               // 1563

// ---------------- scratch (device globals; no allocations) ----------------
// g_h has one extra row (index N_NODES) kept all-zero: padded gather lanes
// point at it and contribute nothing.
__device__ __align__(16) float g_h[(N_NODES + 1) * HID]; // pre-scaled h' = h*dinv
__device__ __align__(16) float g_y[N_NODES * HID];       // post-relu layer output
__device__ int   g_cnt[N_NODES];                         // in-degree (histogram)
__device__ float g_dinv[N_NODES];
__device__ int   g_rowptr[N_NODES];
__device__ int   g_cursor[N_NODES];
__device__ int   g_eidx[N_EDGES];                        // src idx sorted by dst
__device__ int   g_blksum[SCAN_NB];
__device__ float g_stats[2][2 * HID];                    // ping-pong [sum, sumsq]

// ---------------- helpers ----------------
__device__ __forceinline__ void ffma2(unsigned long long& d,
                                      unsigned long long a,
                                      unsigned long long b) {
    asm("fma.rn.f32x2 %0, %1, %2, %0;" : "+l"(d) : "l"(a), "l"(b));
}
__device__ __forceinline__ unsigned long long fpack2(float x) {
    unsigned long long r;
    unsigned u = __float_as_uint(x);
    asm("mov.b64 %0, {%1, %1};" : "=l"(r) : "r"(u));
    return r;
}
__device__ __forceinline__ float2 funpack2(unsigned long long v) {
    unsigned lo, hi;
    asm("mov.b64 {%0, %1}, %2;" : "=r"(lo), "=r"(hi) : "l"(v));
    float2 f;
    f.x = __uint_as_float(lo);
    f.y = __uint_as_float(hi);
    return f;
}
__device__ __forceinline__ unsigned smem_u32(const void* p) {
    return (unsigned)__cvta_generic_to_shared(p);
}
#define CP_ASYNC4(s, g)  asm volatile("cp.async.ca.shared.global [%0], [%1], 4;"  :: "r"(s), "l"(g) : "memory")
#define CP_ASYNC16(s, g) asm volatile("cp.async.cg.shared.global [%0], [%1], 16;" :: "r"(s), "l"(g) : "memory")
#define CP_COMMIT()      asm volatile("cp.async.commit_group;" ::: "memory")
#define CP_WAIT1()       asm volatile("cp.async.wait_group 1;" ::: "memory")

// ---------------- CSR build ----------------
__global__ void hist_kernel(const int* __restrict__ dst) {
    int e = blockIdx.x * blockDim.x + threadIdx.x;
    if (e < N_EDGES) {
        asm volatile("red.global.add.u32 [%0], %1;"
                     :: "l"(&g_cnt[dst[e]]), "r"(1) : "memory");
    }
}

__global__ __launch_bounds__(SCAN_B) void scan1_kernel() {
    __shared__ int sm[SCAN_B];
    int t = threadIdx.x;
    int i = blockIdx.x * SCAN_B + t;
    int v = (i < N_NODES) ? g_cnt[i] : 0;
    sm[t] = v;
    __syncthreads();
    for (int off = 1; off < SCAN_B; off <<= 1) {
        int x = (t >= off) ? sm[t - off] : 0;
        __syncthreads();
        sm[t] += x;
        __syncthreads();
    }
    if (i < N_NODES) g_rowptr[i] = sm[t] - v;  // exclusive (block-local)
    if (t == SCAN_B - 1) g_blksum[blockIdx.x] = sm[t];
}

// scan finalize: each block re-scans the 98 block sums itself, applies offset,
// inits cursor + dinv.
__global__ __launch_bounds__(SCAN_B) void scan23_kernel() {
    __shared__ int sb[128];
    __shared__ int sv[128];
    int t = threadIdx.x;
    if (t < 128) {
        int v = (t < SCAN_NB) ? g_blksum[t] : 0;
        sb[t] = v;
        sv[t] = v;
    }
    __syncthreads();
    for (int off = 1; off < 128; off <<= 1) {
        int x = (t >= off && t < 128) ? sb[t - off] : 0;
        __syncthreads();
        if (t < 128) sb[t] += x;
        __syncthreads();
    }
    int offset = sb[blockIdx.x] - sv[blockIdx.x];
    int i = blockIdx.x * SCAN_B + t;
    if (i < N_NODES) {
        int r = g_rowptr[i] + offset;
        g_rowptr[i] = r;
        g_cursor[i] = r;
        g_dinv[i] = rsqrtf((float)g_cnt[i] + 1.f);
    }
}

// fill: no dinv work, 4-byte scattered store only
__global__ void fill_kernel(const int* __restrict__ src, const int* __restrict__ dst) {
    int e = blockIdx.x * blockDim.x + threadIdx.x;
    if (e < N_EDGES) {
        int s = src[e];
        int d = dst[e];
        int pos = atomicAdd(&g_cursor[d], 1);
        g_eidx[pos] = s;
    }
}

// ---------------- GEMM: h' = (X' @ W) * dinv[row] --------------------------
// Persistent double-buffered: W' = diag(a)W staged once per block; X tiles
// (64 nodes) copied with cp.async while the previous tile computes. BN affine
// is folded into W' and the accumulator seed t[c] = sum_k d[k] W[k][c], so X
// staging is a pure copy. Thread = 4 nodes x 4 cols (FFMA2 pairs).
template <int IN, bool FROM_Y>
__global__ __launch_bounds__(256) void gemm_kernel(const float* __restrict__ X,
                                                   const float* __restrict__ W,
                                                   const float* __restrict__ gam,
                                                   const float* __restrict__ bet,
                                                   int rdp, int wrp) {
    extern __shared__ __align__(16) float smem[];
    float* Ws  = smem;                 // IN * 64
    float* Xs0 = Ws + IN * HID;        // 64 * IN
    float* Xs1 = Xs0 + 64 * IN;        // 64 * IN
    float* s_t  = Xs1 + 64 * IN;       // 64
    float* s_a  = s_t + HID;           // 64
    float* s_dd = s_a + HID;           // 64

    int tid = threadIdx.x;
    if (tid < 2 * HID) g_stats[wrp][tid] = 0.f;

    if (FROM_Y && tid < HID) {
        float mean = g_stats[rdp][tid] * (1.f / N_NODES);
        float var  = g_stats[rdp][HID + tid] * (1.f / N_NODES) - mean * mean;
        float a = gam[tid] * rsqrtf(var + BN_EPS);
        s_a[tid]  = a;
        s_dd[tid] = bet[tid] - mean * a;
    }
    __syncthreads();

    // one-time: stage W' = a[k]*W[k][c], and t[c] = sum_k d[k]*W[k][c]
    for (int i = tid; i < IN * HID; i += 256) {
        float w = W[i];
        if (FROM_Y) w *= s_a[i >> 6];   // k = i/64 (HID==64)
        Ws[i] = w;
    }
    if (tid < HID) {
        float t = 0.f;
        if (FROM_Y) {
#pragma unroll 8
            for (int k = 0; k < IN; k++) t += s_dd[k] * W[k * HID + tid];
        }
        s_t[tid] = t;
    }

    auto stage = [&](float* Xs, int t0) {
        int gbase = t0 * 64;
        if (FROM_Y) {
            // 64 rows x 64 floats, 16B chunks (g_y rows are 256B, 16B aligned)
#pragma unroll
            for (int it = 0; it < 4; it++) {
                int ch  = tid + it * 256;           // 0..1023
                int row = ch >> 4;
                int c4o = (ch & 15) * 4;
                int gr = min(gbase + row, N_NODES - 1);
                CP_ASYNC16(smem_u32(Xs + row * IN + c4o),
                           g_y + (size_t)gr * HID + c4o);
            }
        } else {
            for (int e = tid; e < 64 * IN; e += 256) {
                int row = e / IN, k = e - row * IN;
                int gr = min(gbase + row, N_NODES - 1);
                CP_ASYNC4(smem_u32(Xs + row * IN + k),
                          X + (size_t)gr * IN + k);
            }
        }
        CP_COMMIT();
    };

    float* bufA = Xs0;
    float* bufB = Xs1;
    int tile = blockIdx.x;
    stage(bufA, tile);                  // blockIdx.x < GEMM_NT always

    int tx = tid & 15, ty = tid >> 4;
    int c0 = tx * 4, n0 = ty * 4;

    for (; tile < GEMM_NT; tile += GEMM_GRID) {
        int nxt = tile + GEMM_GRID;
        if (nxt < GEMM_NT) stage(bufB, nxt);
        else               CP_COMMIT();     // keep group count in lockstep
        CP_WAIT1();
        __syncthreads();                    // also orders Ws/s_t on first iter

        ulonglong2 tq = *(const ulonglong2*)&s_t[c0];
        unsigned long long a00 = tq.x, a01 = tq.y;
        unsigned long long a10 = tq.x, a11 = tq.y;
        unsigned long long a20 = tq.x, a21 = tq.y;
        unsigned long long a30 = tq.x, a31 = tq.y;

#pragma unroll 5
        for (int k = 0; k < IN; k++) {
            ulonglong2 wq = *(const ulonglong2*)&Ws[k * HID + c0];
            unsigned long long x0 = fpack2(bufA[(n0 + 0) * IN + k]);
            unsigned long long x1 = fpack2(bufA[(n0 + 1) * IN + k]);
            unsigned long long x2 = fpack2(bufA[(n0 + 2) * IN + k]);
            unsigned long long x3 = fpack2(bufA[(n0 + 3) * IN + k]);
            ffma2(a00, x0, wq.x); ffma2(a01, x0, wq.y);
            ffma2(a10, x1, wq.x); ffma2(a11, x1, wq.y);
            ffma2(a20, x2, wq.x); ffma2(a21, x2, wq.y);
            ffma2(a30, x3, wq.x); ffma2(a31, x3, wq.y);
        }

        int base = tile * 64;
        unsigned long long accs[4][2] = {{a00, a01}, {a10, a11}, {a20, a21}, {a30, a31}};
#pragma unroll
        for (int i = 0; i < 4; i++) {
            int gn = base + n0 + i;
            if (gn < N_NODES) {
                float dv = g_dinv[gn];
                float2 lo = funpack2(accs[i][0]);
                float2 hi = funpack2(accs[i][1]);
                float4 h;
                h.x = lo.x * dv; h.y = lo.y * dv; h.z = hi.x * dv; h.w = hi.y * dv;
                *(float4*)&g_h[gn * HID + c0] = h;
            }
        }

        __syncthreads();                    // all reads of bufA done before restage
        float* tmp = bufA; bufA = bufB; bufB = tmp;
    }
}

// ---------------- gather aggregation + relu + BN stats ----------------
// y[n] = relu( dinv[n]*(h'[n] + Sum h'[src]) + b ). No per-edge weight.
// Padded lanes index the zero row at N_NODES (L1-hot). Metadata prefetched
// one chunk ahead; group-uniform early-outs every 4 edges cut padded work.
__global__ __launch_bounds__(256) void gather_kernel(const float* __restrict__ bias,
                                                     int wrp) {
    __shared__ float s_b[HID];
    __shared__ float sm_s[16][HID + 4];
    __shared__ float sm_q[16][HID + 4];

    int tid   = threadIdx.x;
    int grp   = tid >> 4;
    int lane  = tid & 15;
    unsigned hmask = 0xFFFFu << ((tid & 31) & 16);  // this half-warp's lanes
    int c4    = lane * 4;

    if (tid < HID) s_b[tid] = bias[tid];
    __syncthreads();
    float4 bb = *(const float4*)&s_b[c4];

    float4 s4 = {0.f, 0.f, 0.f, 0.f};
    float4 q4 = {0.f, 0.f, 0.f, 0.f};

    for (int tile = blockIdx.x; tile < N_TILES; tile += GATH_GRID) {
        int n = tile * 16 + grp;
        float dv = g_dinv[n];

        float4 acc = *(const float4*)&g_h[n * HID + c4];  // self term h'[n]

        int start = g_rowptr[n];
        int len   = g_cnt[n];

        // prefetch first metadata chunk (pad -> zero row)
        int pre = (lane < len) ? g_eidx[start + lane] : N_NODES;

        for (int j0 = 0; j0 < len; j0 += 16) {
            int sidx = pre;
            int nj = j0 + 16 + lane;
            pre = (nj < len) ? g_eidx[start + nj] : N_NODES;

#pragma unroll
            for (int j = 0; j < 4; j++) {
                int s = __shfl_sync(hmask, sidx, j, 16);
                float4 hv = *(const float4*)&g_h[s * HID + c4];
                acc.x += hv.x; acc.y += hv.y;
                acc.z += hv.z; acc.w += hv.w;
            }
            if (len > j0 + 4) {
#pragma unroll
                for (int j = 4; j < 8; j++) {
                    int s = __shfl_sync(hmask, sidx, j, 16);
                    float4 hv = *(const float4*)&g_h[s * HID + c4];
                    acc.x += hv.x; acc.y += hv.y;
                    acc.z += hv.z; acc.w += hv.w;
                }
            }
            if (len > j0 + 8) {
#pragma unroll
                for (int j = 8; j < 12; j++) {
                    int s = __shfl_sync(hmask, sidx, j, 16);
                    float4 hv = *(const float4*)&g_h[s * HID + c4];
                    acc.x += hv.x; acc.y += hv.y;
                    acc.z += hv.z; acc.w += hv.w;
                }
            }
            if (len > j0 + 12) {
#pragma unroll
                for (int j = 12; j < 16; j++) {
                    int s = __shfl_sync(hmask, sidx, j, 16);
                    float4 hv = *(const float4*)&g_h[s * HID + c4];
                    acc.x += hv.x; acc.y += hv.y;
                    acc.z += hv.z; acc.w += hv.w;
                }
            }
        }

        acc.x = fmaxf(acc.x * dv + bb.x, 0.f);
        acc.y = fmaxf(acc.y * dv + bb.y, 0.f);
        acc.z = fmaxf(acc.z * dv + bb.z, 0.f);
        acc.w = fmaxf(acc.w * dv + bb.w, 0.f);
        *(float4*)&g_y[n * HID + c4] = acc;

        s4.x += acc.x; q4.x += acc.x * acc.x;
        s4.y += acc.y; q4.y += acc.y * acc.y;
        s4.z += acc.z; q4.z += acc.z * acc.z;
        s4.w += acc.w; q4.w += acc.w * acc.w;
    }

    sm_s[grp][c4 + 0] = s4.x; sm_q[grp][c4 + 0] = q4.x;
    sm_s[grp][c4 + 1] = s4.y; sm_q[grp][c4 + 1] = q4.y;
    sm_s[grp][c4 + 2] = s4.z; sm_q[grp][c4 + 2] = q4.z;
    sm_s[grp][c4 + 3] = s4.w; sm_q[grp][c4 + 3] = q4.w;
    __syncthreads();
    if (tid < HID) {
        float s = 0.f, q = 0.f;
#pragma unroll
        for (int r = 0; r < 16; r++) {
            s += sm_s[r][tid];
            q += sm_q[r][tid];
        }
        asm volatile("red.global.add.f32 [%0], %1;" :: "l"(&g_stats[wrp][tid]), "f"(s) : "memory");
        asm volatile("red.global.add.f32 [%0], %1;" :: "l"(&g_stats[wrp][HID + tid]), "f"(q) : "memory");
    }
}

// ---------------- global add pool (applies final BN affine) ----------------
__global__ __launch_bounds__(256) void pool_kernel(const int* __restrict__ batch,
                                                   float* __restrict__ out,
                                                   const float* __restrict__ gam,
                                                   const float* __restrict__ bet) {
    __shared__ float s_a[HID];
    __shared__ float s_d[HID];
    int tid = threadIdx.x;
    if (tid < HID) {
        float mean = g_stats[1][tid] * (1.f / N_NODES);
        float var  = g_stats[1][HID + tid] * (1.f / N_NODES) - mean * mean;
        float a = gam[tid] * rsqrtf(var + BN_EPS);
        s_a[tid] = a;
        s_d[tid] = bet[tid] - mean * a;
    }
    __syncthreads();

    int grp = tid >> 4, lane = tid & 15;
    int c4 = lane * 4;
    float4 a4 = *(const float4*)&s_a[c4];
    float4 d4 = *(const float4*)&s_d[c4];

    int base = blockIdx.x * 256 + grp * 16;
    float4 run = {0.f, 0.f, 0.f, 0.f};
    int cur = -1;
    for (int i = 0; i < 16; i++) {
        int n = base + i;
        if (n >= N_NODES) break;
        int bt = batch[n];
        if (bt != cur) {
            if (cur >= 0) {
                asm volatile("red.global.add.v4.f32 [%0], {%1,%2,%3,%4};"
                             :: "l"(&out[cur * HID + c4]),
                                "f"(run.x), "f"(run.y), "f"(run.z), "f"(run.w) : "memory");
            }
            run.x = run.y = run.z = run.w = 0.f;
            cur = bt;
        }
        float4 v = *(const float4*)&g_y[n * HID + c4];
        run.x += v.x * a4.x + d4.x;
        run.y += v.y * a4.y + d4.y;
        run.z += v.z * a4.z + d4.z;
        run.w += v.w * a4.w + d4.w;
    }
    if (cur >= 0) {
        asm volatile("red.global.add.v4.f32 [%0], {%1,%2,%3,%4};"
                     :: "l"(&out[cur * HID + c4]),
                        "f"(run.x), "f"(run.y), "f"(run.z), "f"(run.w) : "memory");
    }
}

// ---------------- launch ----------------
extern "C" void kernel_launch(void* const* d_in, const int* in_sizes, int n_in,
                              void* d_out, int out_size) {
    const float* x     = (const float*)d_in[0];
    const int*   src   = (const int*)d_in[1];
    const int*   dst   = (const int*)d_in[2];
    const int*   batch = (const int*)d_in[3];
    const float* W[4];
    const float* b[4];
    const float* g[4];
    const float* be[4];
    for (int i = 0; i < 4; i++) {
        W[i]  = (const float*)d_in[4 + 4 * i];
        b[i]  = (const float*)d_in[5 + 4 * i];
        g[i]  = (const float*)d_in[6 + 4 * i];
        be[i] = (const float*)d_in[7 + 4 * i];
    }
    float* out = (float*)d_out;

    const int NB_EDGES = (N_EDGES + 255) / 256;   // 6250
    const int NB_NODES = (N_NODES + 255) / 256;   // 391

    const int SMEM75 = (75 * HID + 2 * 64 * 75 + 3 * HID) * (int)sizeof(float); // 58368
    const int SMEM64 = (64 * HID + 2 * 64 * 64 + 3 * HID) * (int)sizeof(float); // 49920
    cudaFuncSetAttribute(gemm_kernel<75, false>,
                         cudaFuncAttributeMaxDynamicSharedMemorySize, SMEM75);
    cudaFuncSetAttribute(gemm_kernel<64, true>,
                         cudaFuncAttributeMaxDynamicSharedMemorySize, SMEM64);

    void* p_cnt = nullptr;
    cudaGetSymbolAddress(&p_cnt, g_cnt);
    cudaMemsetAsync(p_cnt, 0, N_NODES * sizeof(int), 0);

    hist_kernel<<<NB_EDGES, 256>>>(dst);
    scan1_kernel<<<SCAN_NB, SCAN_B>>>();
    scan23_kernel<<<SCAN_NB, SCAN_B>>>();   // produces dinv

    // gemm1 before fill so the ncu capture slot lands on it again
    gemm_kernel<75, false><<<GEMM_GRID, 256, SMEM75>>>(x, W[0], nullptr, nullptr, 0, 0);
    fill_kernel<<<NB_EDGES, 256>>>(src, dst);

    // zero row N_NODES of g_h (target of padded gather lanes)
    void* p_h = nullptr;
    cudaGetSymbolAddress(&p_h, g_h);
    cudaMemsetAsync((char*)p_h + (size_t)N_NODES * HID * sizeof(float), 0,
                    HID * sizeof(float), 0);

    gather_kernel<<<GATH_GRID, 256>>>(b[0], 0);

    // layers 2..4
    for (int l = 1; l < 4; l++) {
        gemm_kernel<64, true><<<GEMM_GRID, 256, SMEM64>>>(nullptr, W[l], g[l - 1], be[l - 1],
                                                          (l - 1) & 1, l & 1);
        gather_kernel<<<GATH_GRID, 256>>>(b[l], l & 1);
    }

    cudaMemsetAsync(d_out, 0, (size_t)out_size * sizeof(float), 0);
    pool_kernel<<<NB_NODES, 256>>>(batch, out, g[3], be[3]);
}